// round 7
// baseline (speedup 1.0000x reference)
#include <cuda_runtime.h>
#include <math.h>
#include <stdint.h>

// Problem constants
#define BATCH 64
#define LDIM  1024
#define FFDIM 8192
#define HDIM  256
#define RDIM  4
#define EPSC  1e-4f

// Scratch
__device__ float g_mod[BATCH * FFDIM];     // 2 MB, layout [b][f]
__device__ float g_scale[BATCH * 4];
__device__ float g_weff[RDIM];
__device__ float g_beff;
__device__ float g_magpart[BATCH * 16];

// ---------------------------------------------------------------------------
// tf32 helpers
// ---------------------------------------------------------------------------
__device__ __forceinline__ void tf32_split(float v, uint32_t& hi, uint32_t& lo)
{
    uint32_t h;
    asm("cvt.rna.tf32.f32 %0, %1;" : "=r"(h) : "f"(v));
    float r = v - __uint_as_float(h);
    asm("cvt.rna.tf32.f32 %0, %1;" : "=r"(lo) : "f"(r));
    hi = h;
}

__device__ __forceinline__ void mma8(float* d, const uint32_t* a, const uint32_t* b)
{
    asm volatile(
        "mma.sync.aligned.m16n8k8.row.col.f32.tf32.tf32.f32 "
        "{%0,%1,%2,%3}, {%4,%5,%6,%7}, {%8,%9}, {%0,%1,%2,%3};"
        : "+f"(d[0]), "+f"(d[1]), "+f"(d[2]), "+f"(d[3])
        : "r"(a[0]), "r"(a[1]), "r"(a[2]), "r"(a[3]), "r"(b[0]), "r"(b[1]));
}

// split float4 -> 4 interleaved (hi,lo) uint2, stored as 2x STS.128
__device__ __forceinline__ void store_pair(uint2* p, float4 v)
{
    uint32_t h0, l0, h1, l1, h2, l2, h3, l3;
    tf32_split(v.x, h0, l0);
    tf32_split(v.y, h1, l1);
    tf32_split(v.z, h2, l2);
    tf32_split(v.w, h3, l3);
    *reinterpret_cast<uint4*>(p)     = make_uint4(h0, l0, h1, l1);
    *reinterpret_cast<uint4*>(p + 2) = make_uint4(h2, l2, h3, l3);
}

// ---------------------------------------------------------------------------
// Kernel 1: fused GEMM pair + silu, mma.sync tf32 3-term, split-at-store.
// CTA tile M=64 f x N=64 batch, K-tile 32, double buffer.
// smem: (hi,lo) uint2 tiles, row stride 34 uint2 (conflict-free LDS.64 + STS).
// 256 threads = 8 warps; warp tile M=16 x N=32.
// ---------------------------------------------------------------------------
#define U2STR  34
#define TILEU  (64 * U2STR)          // 2176 uint2
#define STAGEU (3 * TILEU)
#define GEMM_SMEM_BYTES (2 * STAGEU * 8)   // 104448 B

__global__ void __launch_bounds__(256, 1)
k_gemm_mma(const float* __restrict__ x,
           const float* __restrict__ Wt,
           const float* __restrict__ Wg)
{
    extern __shared__ uint2 smem2[];
    const int t    = threadIdx.x;
    const int warp = t >> 5, lane = t & 31;
    const int gid  = lane >> 2, tig = lane & 3;
    const int mb   = (warp & 3) * 16;     // warp M offset (f)
    const int nb   = (warp >> 2) * 32;    // warp N offset (batch)
    const int f0   = blockIdx.x * 64;

    const float4* Wt4 = reinterpret_cast<const float4*>(Wt);
    const float4* Wg4 = reinterpret_cast<const float4*>(Wg);
    const float4* X4  = reinterpret_cast<const float4*>(x);

    // per-thread load/store mapping: row = t>>2, cols {t&3, (t&3)+4} (float4)
    const int srow = t >> 2;
    const int c0   = t & 3;
    const int c1   = c0 + 4;

    float acc[2][4][4];
#pragma unroll
    for (int g = 0; g < 2; g++)
#pragma unroll
        for (int j = 0; j < 4; j++)
#pragma unroll
            for (int c = 0; c < 4; c++) acc[g][j][c] = 0.f;

    float4 wtp[2], wgp[2], xp[2];
    {
        const size_t wb = (size_t)(f0 + srow) * 256;
        wtp[0] = Wt4[wb + c0];      wtp[1] = Wt4[wb + c1];
        wgp[0] = Wg4[wb + c0];      wgp[1] = Wg4[wb + c1];
        xp[0]  = X4[(size_t)srow * 256 + c0];
        xp[1]  = X4[(size_t)srow * 256 + c1];
    }

    for (int kt = 0; kt < 32; ++kt) {
        uint2* st = smem2 + (kt & 1) * STAGEU;
        store_pair(st + srow * U2STR + c0 * 4,              wtp[0]);
        store_pair(st + srow * U2STR + c1 * 4,              wtp[1]);
        store_pair(st + TILEU + srow * U2STR + c0 * 4,      wgp[0]);
        store_pair(st + TILEU + srow * U2STR + c1 * 4,      wgp[1]);
        store_pair(st + 2 * TILEU + srow * U2STR + c0 * 4,  xp[0]);
        store_pair(st + 2 * TILEU + srow * U2STR + c1 * 4,  xp[1]);
        __syncthreads();

        if (kt + 1 < 32) {
            const size_t ko = (size_t)(kt + 1) * 8;
            const size_t wb = (size_t)(f0 + srow) * 256 + ko;
            wtp[0] = Wt4[wb + c0];      wtp[1] = Wt4[wb + c1];
            wgp[0] = Wg4[wb + c0];      wgp[1] = Wg4[wb + c1];
            xp[0]  = X4[(size_t)srow * 256 + ko + c0];
            xp[1]  = X4[(size_t)srow * 256 + ko + c1];
        }

        const uint2* Xb = st + 2 * TILEU;
#pragma unroll
        for (int ks = 0; ks < 4; ++ks) {
            const int ko = ks * 8;
            uint32_t Ah[2][4], Al[2][4], Bh[4][2], Bl[4][2];
#pragma unroll
            for (int g = 0; g < 2; ++g) {
                const uint2* Wb = st + g * TILEU;
                int base = (mb + gid) * U2STR + ko + tig;
                uint2 u0 = Wb[base];
                uint2 u1 = Wb[base + 8 * U2STR];
                uint2 u2 = Wb[base + 4];
                uint2 u3 = Wb[base + 8 * U2STR + 4];
                Ah[g][0] = u0.x; Al[g][0] = u0.y;
                Ah[g][1] = u1.x; Al[g][1] = u1.y;
                Ah[g][2] = u2.x; Al[g][2] = u2.y;
                Ah[g][3] = u3.x; Al[g][3] = u3.y;
            }
#pragma unroll
            for (int j = 0; j < 4; ++j) {
                int base = (nb + j * 8 + gid) * U2STR + ko + tig;
                uint2 v0 = Xb[base];
                uint2 v1 = Xb[base + 4];
                Bh[j][0] = v0.x; Bl[j][0] = v0.y;
                Bh[j][1] = v1.x; Bl[j][1] = v1.y;
            }
#pragma unroll
            for (int g = 0; g < 2; ++g)
#pragma unroll
                for (int j = 0; j < 4; ++j) {
                    mma8(acc[g][j], Ah[g], Bh[j]);
                    mma8(acc[g][j], Ah[g], Bl[j]);
                    mma8(acc[g][j], Al[g], Bh[j]);
                }
        }
        __syncthreads();
    }

    // silu epilogue -> smem transpose -> coalesced float4 stores
    float* sOut = reinterpret_cast<float*>(smem2);   // 64 (b) x 68-stride (f)
#pragma unroll
    for (int j = 0; j < 4; ++j)
#pragma unroll
        for (int c = 0; c < 4; ++c) {
            float tv = acc[0][j][c];
            float gv = acc[1][j][c];
            float o  = tv * __fdividef(gv, 1.0f + __expf(-gv));
            int fl = mb + gid + ((c >> 1) << 3);
            int bl = nb + j * 8 + 2 * tig + (c & 1);
            sOut[bl * 68 + fl] = o;
        }
    __syncthreads();

#pragma unroll
    for (int v = 0; v < 4; ++v) {
        int idx = v * 256 + t;
        int row = idx >> 4, q = idx & 15;
        float4 val = *reinterpret_cast<const float4*>(sOut + row * 68 + q * 4);
        *reinterpret_cast<float4*>(&g_mod[(size_t)row * FFDIM + f0 + q * 4]) = val;
    }
}

// ---------------------------------------------------------------------------
// Block reduction helper (256 threads)
// ---------------------------------------------------------------------------
__device__ __forceinline__ float block_reduce_256(float v, float* sh)
{
#pragma unroll
    for (int o = 16; o > 0; o >>= 1) v += __shfl_xor_sync(0xFFFFFFFFu, v, o);
    int w = threadIdx.x >> 5;
    if ((threadIdx.x & 31) == 0) sh[w] = v;
    __syncthreads();
    if (threadIdx.x < 8) {
        v = sh[threadIdx.x];
#pragma unroll
        for (int o = 4; o > 0; o >>= 1) v += __shfl_xor_sync(0x000000FFu, v, o);
    }
    return v;
}

// ---------------------------------------------------------------------------
// Kernel 2: per-(b,k) normalization scales + conv reductions
// ---------------------------------------------------------------------------
__global__ void k_scale(const float* __restrict__ conv_w,
                        const float* __restrict__ conv_b)
{
    __shared__ float sh[8];
    const int g = blockIdx.x;                 // g = b*4 + k
    const float4* p4 = reinterpret_cast<const float4*>(g_mod + (size_t)g * 2048);
    float4 a = p4[threadIdx.x];
    float4 c = p4[threadIdx.x + 256];
    float s = fabsf(a.x) + fabsf(a.y) + fabsf(a.z) + fabsf(a.w)
            + fabsf(c.x) + fabsf(c.y) + fabsf(c.z) + fabsf(c.w);
    s = block_reduce_256(s, sh);
    if (threadIdx.x == 0)
        g_scale[g] = rsqrtf(s * (1.0f / 2048.0f) + EPSC);

    if (g == 0) {
        if (threadIdx.x < RDIM) {
            float w = 0.f;
#pragma unroll
            for (int i = 0; i < RDIM; i++) w += conv_w[i * RDIM + threadIdx.x];
            g_weff[threadIdx.x] = w;
        }
        if (threadIdx.x == RDIM) {
            float b = 0.f;
#pragma unroll
            for (int i = 0; i < RDIM; i++) b += conv_b[i];
            g_beff = b;
        }
    }
}

// ---------------------------------------------------------------------------
// Kernel 3: per-batch magnitude partial sums. (pipelined global loads)
// ---------------------------------------------------------------------------
__global__ void __launch_bounds__(256)
k_mag(const float* __restrict__ ws, const float* __restrict__ wm)
{
    __shared__ float4 wa4[16][2];
    __shared__ float  sh[8];

    const int b  = blockIdx.y;
    const int i0 = blockIdx.x * 16;
    const int t  = threadIdx.x;

    if (t < 128) {
        int k = t >> 6, r = (t >> 4) & 3, il = t & 15;
        reinterpret_cast<float*>(wa4)[il * 8 + k * 4 + r] =
            g_weff[r] * g_scale[b * 4 + k]
            * g_mod[(size_t)b * FFDIM + k * 2048 + r * 512 + (i0 + il)];
    }

    float sb0[4], sb1[4];
    {
        float s0 = g_scale[b * 4 + 0], s1 = g_scale[b * 4 + 1];
#pragma unroll
        for (int r = 0; r < 4; r++) {
            sb0[r] = s0 * g_mod[(size_t)b * FFDIM + 0 * 2048 + r * 512 + HDIM + t];
            sb1[r] = s1 * g_mod[(size_t)b * FFDIM + 1 * 2048 + r * 512 + HDIM + t];
        }
    }
    __syncthreads();

    const float be = g_beff;
    float sum = 0.f;

    // software pipeline: prefetch il+1 loads
    float wmc0, wmc1; float2 A1c;
    {
        const int pix = (i0 << 8) + t;
        wmc0 = wm[pix]; wmc1 = wm[65536 + pix];
        A1c  = *reinterpret_cast<const float2*>(&ws[131072 + 2 * pix]);
    }
#pragma unroll
    for (int il = 0; il < 16; il++) {
        float wmn0, wmn1; float2 A1n;
        if (il < 15) {
            const int pixn = ((i0 + il + 1) << 8) + t;
            wmn0 = wm[pixn]; wmn1 = wm[65536 + pixn];
            A1n  = *reinterpret_cast<const float2*>(&ws[131072 + 2 * pixn]);
        }
        float4 w0 = wa4[il][0];
        float4 w1 = wa4[il][1];
        float m0 = be, m1 = be;
        m0 = fmaf(w0.x, sb0[0], m0); m0 = fmaf(w0.y, sb0[1], m0);
        m0 = fmaf(w0.z, sb0[2], m0); m0 = fmaf(w0.w, sb0[3], m0);
        m1 = fmaf(w1.x, sb1[0], m1); m1 = fmaf(w1.y, sb1[1], m1);
        m1 = fmaf(w1.z, sb1[2], m1); m1 = fmaf(w1.w, sb1[3], m1);
        m0 *= wmc0;
        m1 *= wmc1;
        float re = A1c.x * m0 - A1c.y * m1;
        float im = A1c.x * m1 - A1c.y * m0;
        sum += sqrtf(fmaf(re, re, fmaf(im, im, EPSC)));
        wmc0 = wmn0; wmc1 = wmn1; A1c = A1n;
    }
    sum = block_reduce_256(sum, sh);
    if (t == 0) g_magpart[b * 16 + blockIdx.x] = sum;
}

// ---------------------------------------------------------------------------
// Kernel 4: final output. (pipelined global loads)
// ---------------------------------------------------------------------------
__global__ void __launch_bounds__(256)
k_final(const float* __restrict__ ws, const float* __restrict__ wm,
        float* __restrict__ out)
{
    __shared__ float4 wa4[16][4];

    const int b  = blockIdx.y;
    const int i0 = blockIdx.x * 16;
    const int t  = threadIdx.x;

    {
        int k = t >> 6, r = (t >> 4) & 3, il = t & 15;
        reinterpret_cast<float*>(wa4)[il * 16 + k * 4 + r] =
            g_weff[r] * g_scale[b * 4 + k]
            * g_mod[(size_t)b * FFDIM + k * 2048 + r * 512 + (i0 + il)];
    }

    float sbv[4][4];
#pragma unroll
    for (int k = 0; k < 4; k++) {
        float sc = g_scale[b * 4 + k];
#pragma unroll
        for (int r = 0; r < 4; r++)
            sbv[k][r] = sc * g_mod[(size_t)b * FFDIM + k * 2048 + r * 512 + HDIM + t];
    }
    __syncthreads();

    float msum = 0.f;
#pragma unroll
    for (int q = 0; q < 16; q++) msum += g_magpart[b * 16 + q];
    const float inv = rsqrtf(msum * (1.0f / 65536.0f) + EPSC);
    const float be = g_beff;

    // software pipeline: prefetch il+1 loads
    float wmc[4]; float2 A0c, A1c;
    {
        const int pix = (i0 << 8) + t;
#pragma unroll
        for (int k = 0; k < 4; k++) wmc[k] = wm[(k << 16) + pix];
        A0c = *reinterpret_cast<const float2*>(&ws[2 * pix]);
        A1c = *reinterpret_cast<const float2*>(&ws[131072 + 2 * pix]);
    }
#pragma unroll
    for (int il = 0; il < 16; il++) {
        float wmn[4]; float2 A0n, A1n;
        if (il < 15) {
            const int pixn = ((i0 + il + 1) << 8) + t;
#pragma unroll
            for (int k = 0; k < 4; k++) wmn[k] = wm[(k << 16) + pixn];
            A0n = *reinterpret_cast<const float2*>(&ws[2 * pixn]);
            A1n = *reinterpret_cast<const float2*>(&ws[131072 + 2 * pixn]);
        }
        const int pix = ((i0 + il) << 8) + t;
        float m[4];
#pragma unroll
        for (int k = 0; k < 4; k++) {
            float4 wk = wa4[il][k];
            float acc = be;
            acc = fmaf(wk.x, sbv[k][0], acc);
            acc = fmaf(wk.y, sbv[k][1], acc);
            acc = fmaf(wk.z, sbv[k][2], acc);
            acc = fmaf(wk.w, sbv[k][3], acc);
            m[k] = wmc[k] * acc;
        }
        float re = A1c.x * m[0] - A1c.y * m[1];
        float im = A1c.x * m[1] - A1c.y * m[0];
        float mwre = fmaf(re, inv, A0c.x);
        float mwim = fmaf(im, inv, A0c.y);
        float den = sqrtf(fmaf(m[2], m[2], fmaf(m[3], m[3], EPSC)));
        out[((size_t)b << 16) + pix] =
            __fdividef(fmaf(mwre, m[2], mwim * m[3]), den);
#pragma unroll
        for (int k = 0; k < 4; k++) wmc[k] = wmn[k];
        A0c = A0n; A1c = A1n;
    }
}

// ---------------------------------------------------------------------------
// Launch
// ---------------------------------------------------------------------------
extern "C" void kernel_launch(void* const* d_in, const int* in_sizes, int n_in,
                              void* d_out, int out_size)
{
    const float* x      = (const float*)d_in[0];
    const float* Wt     = (const float*)d_in[1];
    const float* Wg     = (const float*)d_in[2];
    const float* ws     = (const float*)d_in[3];
    const float* wm     = (const float*)d_in[4];
    const float* conv_w = (const float*)d_in[5];
    const float* conv_b = (const float*)d_in[6];
    float* out = (float*)d_out;

    cudaFuncSetAttribute(k_gemm_mma,
                         cudaFuncAttributeMaxDynamicSharedMemorySize,
                         GEMM_SMEM_BYTES);

    k_gemm_mma<<<FFDIM / 64, 256, GEMM_SMEM_BYTES>>>(x, Wt, Wg);
    k_scale<<<BATCH * 4, 256>>>(conv_w, conv_b);
    k_mag<<<dim3(16, BATCH), 256>>>(ws, wm);
    k_final<<<dim3(16, BATCH), 256>>>(ws, wm, out);
}

// round 9
// speedup vs baseline: 1.0152x; 1.0152x over previous
#include <cuda_runtime.h>
#include <math.h>
#include <stdint.h>

// Problem constants
#define BATCH 64
#define LDIM  1024
#define FFDIM 8192
#define HDIM  256
#define RDIM  4
#define EPSC  1e-4f

// Scratch
__device__ float g_mod[BATCH * FFDIM];     // 2 MB, layout [b][f]
__device__ uint2 g_xs[BATCH * LDIM];       // pre-split x: (tf32_hi, tf32_lo)
__device__ float g_scale[BATCH * 4];
__device__ float g_weff[RDIM];
__device__ float g_beff;
__device__ float g_magpart[BATCH * 16];

// ---------------------------------------------------------------------------
// tf32 helpers
// ---------------------------------------------------------------------------
__device__ __forceinline__ void tf32_split(float v, uint32_t& hi, uint32_t& lo)
{
    uint32_t h;
    asm("cvt.rna.tf32.f32 %0, %1;" : "=r"(h) : "f"(v));
    float r = v - __uint_as_float(h);
    asm("cvt.rna.tf32.f32 %0, %1;" : "=r"(lo) : "f"(r));
    hi = h;
}

__device__ __forceinline__ void mma8(float* d, const uint32_t* a, const uint32_t* b)
{
    asm volatile(
        "mma.sync.aligned.m16n8k8.row.col.f32.tf32.tf32.f32 "
        "{%0,%1,%2,%3}, {%4,%5,%6,%7}, {%8,%9}, {%0,%1,%2,%3};"
        : "+f"(d[0]), "+f"(d[1]), "+f"(d[2]), "+f"(d[3])
        : "r"(a[0]), "r"(a[1]), "r"(a[2]), "r"(a[3]), "r"(b[0]), "r"(b[1]));
}

// ---------------------------------------------------------------------------
// Kernel 0: pre-split x into (hi,lo) tf32 pairs. 64 blocks x 256 thr.
// ---------------------------------------------------------------------------
__global__ void __launch_bounds__(256)
k_xsplit(const float* __restrict__ x)
{
    const int idx = blockIdx.x * 256 + threadIdx.x;   // 0..16383
    float4 v = reinterpret_cast<const float4*>(x)[idx];
    uint32_t h0, l0, h1, l1, h2, l2, h3, l3;
    tf32_split(v.x, h0, l0);
    tf32_split(v.y, h1, l1);
    tf32_split(v.z, h2, l2);
    tf32_split(v.w, h3, l3);
    uint4* o = reinterpret_cast<uint4*>(g_xs);
    o[idx * 2]     = make_uint4(h0, l0, h1, l1);
    o[idx * 2 + 1] = make_uint4(h2, l2, h3, l3);
}

// ---------------------------------------------------------------------------
// Kernel 1: fused GEMM pair + silu, mma.sync tf32 3-term.
// W tiles: float, split-at-use (Round-6 proven). x tile: pre-split uint2.
// CTA tile M=64 f x N=64 batch, K-tile 32, double buffer, 256 thr (8 warps).
// ---------------------------------------------------------------------------
#define TSTR   36                    // W tile row stride (floats)
#define XSTR   34                    // x tile row stride (uint2)
#define WT_OFF 0
#define WG_OFF 9216                  // 64*36*4
#define X_OFF  18432
#define STAGE_BYTES (18432 + 64 * XSTR * 8)   // 35840
#define GEMM_SMEM_BYTES (2 * STAGE_BYTES)     // 71680

__global__ void __launch_bounds__(256, 1)
k_gemm_mma(const float* __restrict__ Wt,
           const float* __restrict__ Wg)
{
    extern __shared__ __align__(16) char smem[];
    const int t    = threadIdx.x;
    const int warp = t >> 5, lane = t & 31;
    const int gid  = lane >> 2, tig = lane & 3;
    const int mb   = (warp & 3) * 16;     // warp M offset (f)
    const int nb   = (warp >> 2) * 32;    // warp N offset (batch)
    const int f0   = blockIdx.x * 64;

    const float4* Wt4 = reinterpret_cast<const float4*>(Wt);
    const float4* Wg4 = reinterpret_cast<const float4*>(Wg);
    const uint4*  Xs4 = reinterpret_cast<const uint4*>(g_xs);

    // x loader mapping: row = t>>2 (0..63), col base (t&3)*8 uint2 (elements)
    const int xrow = t >> 2;
    const int xcb  = (t & 3) * 8;

    float acc[2][4][4];
#pragma unroll
    for (int g = 0; g < 2; g++)
#pragma unroll
        for (int j = 0; j < 4; j++)
#pragma unroll
            for (int c = 0; c < 4; c++) acc[g][j][c] = 0.f;

    float4 wtp[2], wgp[2];
    uint4  xq[4];
    {
#pragma unroll
        for (int q = 0; q < 2; q++) {
            int idx = q * 256 + t, row = idx >> 3, col = idx & 7;
            wtp[q] = Wt4[(size_t)(f0 + row) * 256 + col];
            wgp[q] = Wg4[(size_t)(f0 + row) * 256 + col];
        }
        int xb = xrow * 512 + (xcb >> 1);
#pragma unroll
        for (int j = 0; j < 4; j++) xq[j] = Xs4[xb + j];
    }

    for (int kt = 0; kt < 32; ++kt) {
        char* stg = smem + (kt & 1) * STAGE_BYTES;
        float* swt = reinterpret_cast<float*>(stg + WT_OFF);
        float* swg = reinterpret_cast<float*>(stg + WG_OFF);
        uint2* sx  = reinterpret_cast<uint2*>(stg + X_OFF);
#pragma unroll
        for (int q = 0; q < 2; q++) {
            int idx = q * 256 + t, row = idx >> 3, col = idx & 7;
            *reinterpret_cast<float4*>(&swt[row * TSTR + col * 4]) = wtp[q];
            *reinterpret_cast<float4*>(&swg[row * TSTR + col * 4]) = wgp[q];
        }
#pragma unroll
        for (int j = 0; j < 4; j++)
            *reinterpret_cast<uint4*>(&sx[xrow * XSTR + xcb + 2 * j]) = xq[j];
        __syncthreads();

        if (kt + 1 < 32) {
            const size_t ko = (size_t)(kt + 1) * 8;   // float4 units (W)
#pragma unroll
            for (int q = 0; q < 2; q++) {
                int idx = q * 256 + t, row = idx >> 3, col = idx & 7;
                wtp[q] = Wt4[(size_t)(f0 + row) * 256 + ko + col];
                wgp[q] = Wg4[(size_t)(f0 + row) * 256 + ko + col];
            }
            // x advances 32 elements per k-tile = 16 uint4
            int xb = xrow * 512 + (kt + 1) * 16 + (xcb >> 1);
#pragma unroll
            for (int j = 0; j < 4; j++) xq[j] = Xs4[xb + j];
        }

#pragma unroll
        for (int ks = 0; ks < 4; ++ks) {
            const int ko = ks * 8;
            uint32_t Ah[2][4], Al[2][4], Bh[4][2], Bl[4][2];
#pragma unroll
            for (int g = 0; g < 2; ++g) {
                const float* Wb = (g == 0) ? swt : swg;
                int r0 = mb + gid;
                float v0 = Wb[r0 * TSTR + ko + tig];
                float v1 = Wb[(r0 + 8) * TSTR + ko + tig];
                float v2 = Wb[r0 * TSTR + ko + tig + 4];
                float v3 = Wb[(r0 + 8) * TSTR + ko + tig + 4];
                tf32_split(v0, Ah[g][0], Al[g][0]);
                tf32_split(v1, Ah[g][1], Al[g][1]);
                tf32_split(v2, Ah[g][2], Al[g][2]);
                tf32_split(v3, Ah[g][3], Al[g][3]);
            }
#pragma unroll
            for (int j = 0; j < 4; ++j) {
                int base = (nb + j * 8 + gid) * XSTR + ko + tig;
                uint2 v0 = sx[base];
                uint2 v1 = sx[base + 4];
                Bh[j][0] = v0.x; Bl[j][0] = v0.y;
                Bh[j][1] = v1.x; Bl[j][1] = v1.y;
            }
#pragma unroll
            for (int g = 0; g < 2; ++g)
#pragma unroll
                for (int j = 0; j < 4; ++j) {
                    mma8(acc[g][j], Ah[g], Bh[j]);
                    mma8(acc[g][j], Ah[g], Bl[j]);
                    mma8(acc[g][j], Al[g], Bh[j]);
                }
        }
    }

    // silu epilogue -> smem transpose -> coalesced float4 stores
    __syncthreads();
    float* sOut = reinterpret_cast<float*>(smem);   // 64 (b) x 68-stride (f)
#pragma unroll
    for (int j = 0; j < 4; ++j)
#pragma unroll
        for (int c = 0; c < 4; ++c) {
            float tv = acc[0][j][c];
            float gv = acc[1][j][c];
            float o  = tv * __fdividef(gv, 1.0f + __expf(-gv));
            int fl = mb + gid + ((c >> 1) << 3);
            int bl = nb + j * 8 + 2 * tig + (c & 1);
            sOut[bl * 68 + fl] = o;
        }
    __syncthreads();

#pragma unroll
    for (int v = 0; v < 4; ++v) {
        int idx = v * 256 + t;
        int row = idx >> 4, q = idx & 15;
        float4 val = *reinterpret_cast<const float4*>(sOut + row * 68 + q * 4);
        *reinterpret_cast<float4*>(&g_mod[(size_t)row * FFDIM + f0 + q * 4]) = val;
    }
}

// ---------------------------------------------------------------------------
// Block reduction helper (256 threads)
// ---------------------------------------------------------------------------
__device__ __forceinline__ float block_reduce_256(float v, float* sh)
{
#pragma unroll
    for (int o = 16; o > 0; o >>= 1) v += __shfl_xor_sync(0xFFFFFFFFu, v, o);
    int w = threadIdx.x >> 5;
    if ((threadIdx.x & 31) == 0) sh[w] = v;
    __syncthreads();
    if (threadIdx.x < 8) {
        v = sh[threadIdx.x];
#pragma unroll
        for (int o = 4; o > 0; o >>= 1) v += __shfl_xor_sync(0x000000FFu, v, o);
    }
    return v;
}

// ---------------------------------------------------------------------------
// Kernel 2: per-(b,k) normalization scales + conv reductions
// ---------------------------------------------------------------------------
__global__ void k_scale(const float* __restrict__ conv_w,
                        const float* __restrict__ conv_b)
{
    __shared__ float sh[8];
    const int g = blockIdx.x;                 // g = b*4 + k
    const float4* p4 = reinterpret_cast<const float4*>(g_mod + (size_t)g * 2048);
    float4 a = p4[threadIdx.x];
    float4 c = p4[threadIdx.x + 256];
    float s = fabsf(a.x) + fabsf(a.y) + fabsf(a.z) + fabsf(a.w)
            + fabsf(c.x) + fabsf(c.y) + fabsf(c.z) + fabsf(c.w);
    s = block_reduce_256(s, sh);
    if (threadIdx.x == 0)
        g_scale[g] = rsqrtf(s * (1.0f / 2048.0f) + EPSC);

    if (g == 0) {
        if (threadIdx.x < RDIM) {
            float w = 0.f;
#pragma unroll
            for (int i = 0; i < RDIM; i++) w += conv_w[i * RDIM + threadIdx.x];
            g_weff[threadIdx.x] = w;
        }
        if (threadIdx.x == RDIM) {
            float b = 0.f;
#pragma unroll
            for (int i = 0; i < RDIM; i++) b += conv_b[i];
            g_beff = b;
        }
    }
}

// ---------------------------------------------------------------------------
// Kernel 3: per-batch magnitude partial sums. (pipelined global loads)
// ---------------------------------------------------------------------------
__global__ void __launch_bounds__(256)
k_mag(const float* __restrict__ ws, const float* __restrict__ wm)
{
    __shared__ float4 wa4[16][2];
    __shared__ float  sh[8];

    const int b  = blockIdx.y;
    const int i0 = blockIdx.x * 16;
    const int t  = threadIdx.x;

    if (t < 128) {
        int k = t >> 6, r = (t >> 4) & 3, il = t & 15;
        reinterpret_cast<float*>(wa4)[il * 8 + k * 4 + r] =
            g_weff[r] * g_scale[b * 4 + k]
            * g_mod[(size_t)b * FFDIM + k * 2048 + r * 512 + (i0 + il)];
    }

    float sb0[4], sb1[4];
    {
        float s0 = g_scale[b * 4 + 0], s1 = g_scale[b * 4 + 1];
#pragma unroll
        for (int r = 0; r < 4; r++) {
            sb0[r] = s0 * g_mod[(size_t)b * FFDIM + 0 * 2048 + r * 512 + HDIM + t];
            sb1[r] = s1 * g_mod[(size_t)b * FFDIM + 1 * 2048 + r * 512 + HDIM + t];
        }
    }
    __syncthreads();

    const float be = g_beff;
    float sum = 0.f;

    float wmc0, wmc1; float2 A1c;
    {
        const int pix = (i0 << 8) + t;
        wmc0 = wm[pix]; wmc1 = wm[65536 + pix];
        A1c  = *reinterpret_cast<const float2*>(&ws[131072 + 2 * pix]);
    }
#pragma unroll
    for (int il = 0; il < 16; il++) {
        float wmn0, wmn1; float2 A1n;
        if (il < 15) {
            const int pixn = ((i0 + il + 1) << 8) + t;
            wmn0 = wm[pixn]; wmn1 = wm[65536 + pixn];
            A1n  = *reinterpret_cast<const float2*>(&ws[131072 + 2 * pixn]);
        }
        float4 w0 = wa4[il][0];
        float4 w1 = wa4[il][1];
        float m0 = be, m1 = be;
        m0 = fmaf(w0.x, sb0[0], m0); m0 = fmaf(w0.y, sb0[1], m0);
        m0 = fmaf(w0.z, sb0[2], m0); m0 = fmaf(w0.w, sb0[3], m0);
        m1 = fmaf(w1.x, sb1[0], m1); m1 = fmaf(w1.y, sb1[1], m1);
        m1 = fmaf(w1.z, sb1[2], m1); m1 = fmaf(w1.w, sb1[3], m1);
        m0 *= wmc0;
        m1 *= wmc1;
        float re = A1c.x * m0 - A1c.y * m1;
        float im = A1c.x * m1 - A1c.y * m0;
        sum += sqrtf(fmaf(re, re, fmaf(im, im, EPSC)));
        wmc0 = wmn0; wmc1 = wmn1; A1c = A1n;
    }
    sum = block_reduce_256(sum, sh);
    if (t == 0) g_magpart[b * 16 + blockIdx.x] = sum;
}

// ---------------------------------------------------------------------------
// Kernel 4: final output. (pipelined global loads)
// ---------------------------------------------------------------------------
__global__ void __launch_bounds__(256)
k_final(const float* __restrict__ ws, const float* __restrict__ wm,
        float* __restrict__ out)
{
    __shared__ float4 wa4[16][4];

    const int b  = blockIdx.y;
    const int i0 = blockIdx.x * 16;
    const int t  = threadIdx.x;

    {
        int k = t >> 6, r = (t >> 4) & 3, il = t & 15;
        reinterpret_cast<float*>(wa4)[il * 16 + k * 4 + r] =
            g_weff[r] * g_scale[b * 4 + k]
            * g_mod[(size_t)b * FFDIM + k * 2048 + r * 512 + (i0 + il)];
    }

    float sbv[4][4];
#pragma unroll
    for (int k = 0; k < 4; k++) {
        float sc = g_scale[b * 4 + k];
#pragma unroll
        for (int r = 0; r < 4; r++)
            sbv[k][r] = sc * g_mod[(size_t)b * FFDIM + k * 2048 + r * 512 + HDIM + t];
    }
    __syncthreads();

    float msum = 0.f;
#pragma unroll
    for (int q = 0; q < 16; q++) msum += g_magpart[b * 16 + q];
    const float inv = rsqrtf(msum * (1.0f / 65536.0f) + EPSC);
    const float be = g_beff;

    float wmc[4]; float2 A0c, A1c;
    {
        const int pix = (i0 << 8) + t;
#pragma unroll
        for (int k = 0; k < 4; k++) wmc[k] = wm[(k << 16) + pix];
        A0c = *reinterpret_cast<const float2*>(&ws[2 * pix]);
        A1c = *reinterpret_cast<const float2*>(&ws[131072 + 2 * pix]);
    }
#pragma unroll
    for (int il = 0; il < 16; il++) {
        float wmn[4]; float2 A0n, A1n;
        if (il < 15) {
            const int pixn = ((i0 + il + 1) << 8) + t;
#pragma unroll
            for (int k = 0; k < 4; k++) wmn[k] = wm[(k << 16) + pixn];
            A0n = *reinterpret_cast<const float2*>(&ws[2 * pixn]);
            A1n = *reinterpret_cast<const float2*>(&ws[131072 + 2 * pixn]);
        }
        const int pix = ((i0 + il) << 8) + t;
        float m[4];
#pragma unroll
        for (int k = 0; k < 4; k++) {
            float4 wk = wa4[il][k];
            float acc = be;
            acc = fmaf(wk.x, sbv[k][0], acc);
            acc = fmaf(wk.y, sbv[k][1], acc);
            acc = fmaf(wk.z, sbv[k][2], acc);
            acc = fmaf(wk.w, sbv[k][3], acc);
            m[k] = wmc[k] * acc;
        }
        float re = A1c.x * m[0] - A1c.y * m[1];
        float im = A1c.x * m[1] - A1c.y * m[0];
        float mwre = fmaf(re, inv, A0c.x);
        float mwim = fmaf(im, inv, A0c.y);
        float den = sqrtf(fmaf(m[2], m[2], fmaf(m[3], m[3], EPSC)));
        out[((size_t)b << 16) + pix] =
            __fdividef(fmaf(mwre, m[2], mwim * m[3]), den);
#pragma unroll
        for (int k = 0; k < 4; k++) wmc[k] = wmn[k];
        A0c = A0n; A1c = A1n;
    }
}

// ---------------------------------------------------------------------------
// Launch
// ---------------------------------------------------------------------------
extern "C" void kernel_launch(void* const* d_in, const int* in_sizes, int n_in,
                              void* d_out, int out_size)
{
    const float* x      = (const float*)d_in[0];
    const float* Wt     = (const float*)d_in[1];
    const float* Wg     = (const float*)d_in[2];
    const float* ws     = (const float*)d_in[3];
    const float* wm     = (const float*)d_in[4];
    const float* conv_w = (const float*)d_in[5];
    const float* conv_b = (const float*)d_in[6];
    float* out = (float*)d_out;

    cudaFuncSetAttribute(k_gemm_mma,
                         cudaFuncAttributeMaxDynamicSharedMemorySize,
                         GEMM_SMEM_BYTES);

    k_xsplit<<<64, 256>>>(x);
    k_gemm_mma<<<FFDIM / 64, 256, GEMM_SMEM_BYTES>>>(Wt, Wg);
    k_scale<<<BATCH * 4, 256>>>(conv_w, conv_b);
    k_mag<<<dim3(16, BATCH), 256>>>(ws, wm);
    k_final<<<dim3(16, BATCH), 256>>>(ws, wm, out);
}

// round 10
// speedup vs baseline: 1.5680x; 1.5446x over previous
#include <cuda_runtime.h>
#include <math.h>
#include <stdint.h>

// Problem constants
#define BATCH 64
#define LDIM  1024
#define FFDIM 8192
#define HDIM  256
#define RDIM  4
#define EPSC  1e-4f

// Scratch
__device__ float    g_mod[BATCH * FFDIM];   // 2 MB, layout [b][f]
__device__ uint32_t g_xh[BATCH * 512];      // x hi fp16x2 pairs
__device__ uint32_t g_xl[BATCH * 512];      // x lo (scaled 2^10) fp16x2 pairs
__device__ float    g_scale[BATCH * 4];
__device__ float    g_weff[RDIM];
__device__ float    g_beff;
__device__ float    g_magpart[BATCH * 16];

// ---------------------------------------------------------------------------
// fp16 scaled-split helpers
// ---------------------------------------------------------------------------
__device__ __forceinline__ void f16split(float v, uint16_t& h, uint16_t& l)
{
    uint16_t hh;
    asm("cvt.rn.f16.f32 %0, %1;" : "=h"(hh) : "f"(v));
    float hf;
    asm("cvt.f32.f16 %0, %1;" : "=f"(hf) : "h"(hh));
    float r = (v - hf) * 1024.0f;            // scale keeps lo in normal range
    asm("cvt.rn.f16.f32 %0, %1;" : "=h"(l) : "f"(r));
    h = hh;
}
__device__ __forceinline__ uint32_t packh(uint16_t a, uint16_t b)
{
    uint32_t w;
    asm("mov.b32 %0, {%1, %2};" : "=r"(w) : "h"(a), "h"(b));
    return w;
}
__device__ __forceinline__ void split4(float4 v, uint32_t& h01, uint32_t& h23,
                                       uint32_t& l01, uint32_t& l23)
{
    uint16_t h0, h1, h2, h3, l0, l1, l2, l3;
    f16split(v.x, h0, l0);
    f16split(v.y, h1, l1);
    f16split(v.z, h2, l2);
    f16split(v.w, h3, l3);
    h01 = packh(h0, h1); h23 = packh(h2, h3);
    l01 = packh(l0, l1); l23 = packh(l2, l3);
}

__device__ __forceinline__ void mma16(float* d, const uint32_t* a, const uint32_t* b)
{
    asm volatile(
        "mma.sync.aligned.m16n8k16.row.col.f32.f16.f16.f32 "
        "{%0,%1,%2,%3}, {%4,%5,%6,%7}, {%8,%9}, {%0,%1,%2,%3};"
        : "+f"(d[0]), "+f"(d[1]), "+f"(d[2]), "+f"(d[3])
        : "r"(a[0]), "r"(a[1]), "r"(a[2]), "r"(a[3]), "r"(b[0]), "r"(b[1]));
}

// ---------------------------------------------------------------------------
// Kernel 0: pre-split x into packed fp16x2 (hi, scaled-lo). 64 x 256.
// ---------------------------------------------------------------------------
__global__ void __launch_bounds__(256)
k_xsplit(const float* __restrict__ x)
{
    const int idx = blockIdx.x * 256 + threadIdx.x;   // 0..16383 float4s
    float4 v = reinterpret_cast<const float4*>(x)[idx];
    uint32_t h01, h23, l01, l23;
    split4(v, h01, h23, l01, l23);
    reinterpret_cast<uint2*>(g_xh)[idx] = make_uint2(h01, h23);
    reinterpret_cast<uint2*>(g_xl)[idx] = make_uint2(l01, l23);
}

// ---------------------------------------------------------------------------
// Kernel 1: fused GEMM pair + silu via fp16 m16n8k16, dual-accumulator split.
// CTA tile M=64 f x N=64 batch, K-tile 32 (2 k16 steps), double buffer.
// smem: packed fp16x2 tiles, row stride 20 words (conflict-free LDS.32).
// 256 threads = 8 warps; warp tile M=16 x N=32.
// ---------------------------------------------------------------------------
#define WSTR   20                    // words per tile row (16 used + 4 pad)
#define TILE_W (64 * WSTR)           // 1280 words per tile
#define ST_WTH 0
#define ST_WTL (1 * TILE_W)
#define ST_WGH (2 * TILE_W)
#define ST_WGL (3 * TILE_W)
#define ST_XH  (4 * TILE_W)
#define ST_XL  (5 * TILE_W)
#define STAGE_WORDS (6 * TILE_W)     // 7680 words = 30720 B
#define GEMM_SMEM_BYTES (2 * STAGE_WORDS * 4)   // 61440 B

__global__ void __launch_bounds__(256, 1)
k_gemm_mma(const float* __restrict__ Wt,
           const float* __restrict__ Wg)
{
    extern __shared__ uint32_t smw[];
    const int t    = threadIdx.x;
    const int warp = t >> 5, lane = t & 31;
    const int gid  = lane >> 2, tig = lane & 3;
    const int mb   = (warp & 3) * 16;     // warp M offset (f)
    const int nb   = (warp >> 2) * 32;    // warp N offset (batch)
    const int f0   = blockIdx.x * 64;

    const float4* Wt4 = reinterpret_cast<const float4*>(Wt);
    const float4* Wg4 = reinterpret_cast<const float4*>(Wg);
    const uint4*  Xh4 = reinterpret_cast<const uint4*>(g_xh);
    const uint4*  Xl4 = reinterpret_cast<const uint4*>(g_xl);

    const int xrow = t >> 2;          // batch row 0..63
    const int xc   = t & 3;           // 4-word group 0..3

    float acc1[2][4][4], acc2[2][4][4];
#pragma unroll
    for (int g = 0; g < 2; g++)
#pragma unroll
        for (int j = 0; j < 4; j++)
#pragma unroll
            for (int c = 0; c < 4; c++) { acc1[g][j][c] = 0.f; acc2[g][j][c] = 0.f; }

    float4 wtp[2], wgp[2];
    uint4  xhq, xlq;
    {
#pragma unroll
        for (int q = 0; q < 2; q++) {
            int idx = q * 256 + t, row = idx >> 3, col = idx & 7;
            wtp[q] = Wt4[(size_t)(f0 + row) * 256 + col];
            wgp[q] = Wg4[(size_t)(f0 + row) * 256 + col];
        }
        xhq = Xh4[xrow * 128 + xc];
        xlq = Xl4[xrow * 128 + xc];
    }

    for (int kt = 0; kt < 32; ++kt) {
        uint32_t* st = smw + (kt & 1) * STAGE_WORDS;
        // split+store W tiles
#pragma unroll
        for (int q = 0; q < 2; q++) {
            int idx = q * 256 + t, row = idx >> 3, col = idx & 7;
            int off = row * WSTR + col * 2;
            uint32_t h01, h23, l01, l23;
            split4(wtp[q], h01, h23, l01, l23);
            *reinterpret_cast<uint2*>(&st[ST_WTH + off]) = make_uint2(h01, h23);
            *reinterpret_cast<uint2*>(&st[ST_WTL + off]) = make_uint2(l01, l23);
            split4(wgp[q], h01, h23, l01, l23);
            *reinterpret_cast<uint2*>(&st[ST_WGH + off]) = make_uint2(h01, h23);
            *reinterpret_cast<uint2*>(&st[ST_WGL + off]) = make_uint2(l01, l23);
        }
        // store x tiles (already split)
        *reinterpret_cast<uint4*>(&st[ST_XH + xrow * WSTR + xc * 4]) = xhq;
        *reinterpret_cast<uint4*>(&st[ST_XL + xrow * WSTR + xc * 4]) = xlq;
        __syncthreads();

        if (kt + 1 < 32) {
            const size_t ko = (size_t)(kt + 1) * 8;   // float4 units
#pragma unroll
            for (int q = 0; q < 2; q++) {
                int idx = q * 256 + t, row = idx >> 3, col = idx & 7;
                wtp[q] = Wt4[(size_t)(f0 + row) * 256 + ko + col];
                wgp[q] = Wg4[(size_t)(f0 + row) * 256 + ko + col];
            }
            xhq = Xh4[xrow * 128 + (kt + 1) * 4 + xc];
            xlq = Xl4[xrow * 128 + (kt + 1) * 4 + xc];
        }

#pragma unroll
        for (int ks = 0; ks < 2; ++ks) {
            const int kb = ks * 8;    // pair offset within tile
            uint32_t Ah[2][4], Al[2][4], Bh[4][2], Bl[4][2];
#pragma unroll
            for (int g = 0; g < 2; ++g) {
                const uint32_t* th = st + (g ? ST_WGH : ST_WTH);
                const uint32_t* tl = st + (g ? ST_WGL : ST_WTL);
                int r0 = (mb + gid) * WSTR + kb + tig;
                int r1 = r0 + 8 * WSTR;
                Ah[g][0] = th[r0];     Ah[g][1] = th[r1];
                Ah[g][2] = th[r0 + 4]; Ah[g][3] = th[r1 + 4];
                Al[g][0] = tl[r0];     Al[g][1] = tl[r1];
                Al[g][2] = tl[r0 + 4]; Al[g][3] = tl[r1 + 4];
            }
#pragma unroll
            for (int j = 0; j < 4; ++j) {
                int bb = (nb + j * 8 + gid) * WSTR + kb + tig;
                Bh[j][0] = st[ST_XH + bb]; Bh[j][1] = st[ST_XH + bb + 4];
                Bl[j][0] = st[ST_XL + bb]; Bl[j][1] = st[ST_XL + bb + 4];
            }
#pragma unroll
            for (int g = 0; g < 2; ++g)
#pragma unroll
                for (int j = 0; j < 4; ++j) {
                    mma16(acc1[g][j], Ah[g], Bh[j]);
                    mma16(acc2[g][j], Ah[g], Bl[j]);
                    mma16(acc2[g][j], Al[g], Bh[j]);
                }
        }
    }

    // merge scaled residual terms, silu, transpose, coalesced store
    __syncthreads();
    float* sOut = reinterpret_cast<float*>(smw);   // 64 (b) x 68-stride (f)
#pragma unroll
    for (int j = 0; j < 4; ++j)
#pragma unroll
        for (int c = 0; c < 4; ++c) {
            float tv = fmaf(acc2[0][j][c], 1.0f / 1024.0f, acc1[0][j][c]);
            float gv = fmaf(acc2[1][j][c], 1.0f / 1024.0f, acc1[1][j][c]);
            float o  = tv * __fdividef(gv, 1.0f + __expf(-gv));
            int fl = mb + gid + ((c >> 1) << 3);
            int bl = nb + j * 8 + 2 * tig + (c & 1);
            sOut[bl * 68 + fl] = o;
        }
    __syncthreads();

#pragma unroll
    for (int v = 0; v < 4; ++v) {
        int idx = v * 256 + t;
        int row = idx >> 4, q = idx & 15;
        float4 val = *reinterpret_cast<const float4*>(sOut + row * 68 + q * 4);
        *reinterpret_cast<float4*>(&g_mod[(size_t)row * FFDIM + f0 + q * 4]) = val;
    }
}

// ---------------------------------------------------------------------------
// Block reduction helper (256 threads)
// ---------------------------------------------------------------------------
__device__ __forceinline__ float block_reduce_256(float v, float* sh)
{
#pragma unroll
    for (int o = 16; o > 0; o >>= 1) v += __shfl_xor_sync(0xFFFFFFFFu, v, o);
    int w = threadIdx.x >> 5;
    if ((threadIdx.x & 31) == 0) sh[w] = v;
    __syncthreads();
    if (threadIdx.x < 8) {
        v = sh[threadIdx.x];
#pragma unroll
        for (int o = 4; o > 0; o >>= 1) v += __shfl_xor_sync(0x000000FFu, v, o);
    }
    return v;
}

// ---------------------------------------------------------------------------
// Kernel 2: per-(b,k) normalization scales + conv reductions
// ---------------------------------------------------------------------------
__global__ void k_scale(const float* __restrict__ conv_w,
                        const float* __restrict__ conv_b)
{
    __shared__ float sh[8];
    const int g = blockIdx.x;                 // g = b*4 + k
    const float4* p4 = reinterpret_cast<const float4*>(g_mod + (size_t)g * 2048);
    float4 a = p4[threadIdx.x];
    float4 c = p4[threadIdx.x + 256];
    float s = fabsf(a.x) + fabsf(a.y) + fabsf(a.z) + fabsf(a.w)
            + fabsf(c.x) + fabsf(c.y) + fabsf(c.z) + fabsf(c.w);
    s = block_reduce_256(s, sh);
    if (threadIdx.x == 0)
        g_scale[g] = rsqrtf(s * (1.0f / 2048.0f) + EPSC);

    if (g == 0) {
        if (threadIdx.x < RDIM) {
            float w = 0.f;
#pragma unroll
            for (int i = 0; i < RDIM; i++) w += conv_w[i * RDIM + threadIdx.x];
            g_weff[threadIdx.x] = w;
        }
        if (threadIdx.x == RDIM) {
            float b = 0.f;
#pragma unroll
            for (int i = 0; i < RDIM; i++) b += conv_b[i];
            g_beff = b;
        }
    }
}

// ---------------------------------------------------------------------------
// Kernel 3: per-batch magnitude partial sums. (pipelined global loads)
// ---------------------------------------------------------------------------
__global__ void __launch_bounds__(256)
k_mag(const float* __restrict__ ws, const float* __restrict__ wm)
{
    __shared__ float4 wa4[16][2];
    __shared__ float  sh[8];

    const int b  = blockIdx.y;
    const int i0 = blockIdx.x * 16;
    const int t  = threadIdx.x;

    if (t < 128) {
        int k = t >> 6, r = (t >> 4) & 3, il = t & 15;
        reinterpret_cast<float*>(wa4)[il * 8 + k * 4 + r] =
            g_weff[r] * g_scale[b * 4 + k]
            * g_mod[(size_t)b * FFDIM + k * 2048 + r * 512 + (i0 + il)];
    }

    float sb0[4], sb1[4];
    {
        float s0 = g_scale[b * 4 + 0], s1 = g_scale[b * 4 + 1];
#pragma unroll
        for (int r = 0; r < 4; r++) {
            sb0[r] = s0 * g_mod[(size_t)b * FFDIM + 0 * 2048 + r * 512 + HDIM + t];
            sb1[r] = s1 * g_mod[(size_t)b * FFDIM + 1 * 2048 + r * 512 + HDIM + t];
        }
    }
    __syncthreads();

    const float be = g_beff;
    float sum = 0.f;

    float wmc0, wmc1; float2 A1c;
    {
        const int pix = (i0 << 8) + t;
        wmc0 = wm[pix]; wmc1 = wm[65536 + pix];
        A1c  = *reinterpret_cast<const float2*>(&ws[131072 + 2 * pix]);
    }
#pragma unroll
    for (int il = 0; il < 16; il++) {
        float wmn0, wmn1; float2 A1n;
        if (il < 15) {
            const int pixn = ((i0 + il + 1) << 8) + t;
            wmn0 = wm[pixn]; wmn1 = wm[65536 + pixn];
            A1n  = *reinterpret_cast<const float2*>(&ws[131072 + 2 * pixn]);
        }
        float4 w0 = wa4[il][0];
        float4 w1 = wa4[il][1];
        float m0 = be, m1 = be;
        m0 = fmaf(w0.x, sb0[0], m0); m0 = fmaf(w0.y, sb0[1], m0);
        m0 = fmaf(w0.z, sb0[2], m0); m0 = fmaf(w0.w, sb0[3], m0);
        m1 = fmaf(w1.x, sb1[0], m1); m1 = fmaf(w1.y, sb1[1], m1);
        m1 = fmaf(w1.z, sb1[2], m1); m1 = fmaf(w1.w, sb1[3], m1);
        m0 *= wmc0;
        m1 *= wmc1;
        float re = A1c.x * m0 - A1c.y * m1;
        float im = A1c.x * m1 - A1c.y * m0;
        sum += sqrtf(fmaf(re, re, fmaf(im, im, EPSC)));
        wmc0 = wmn0; wmc1 = wmn1; A1c = A1n;
    }
    sum = block_reduce_256(sum, sh);
    if (t == 0) g_magpart[b * 16 + blockIdx.x] = sum;
}

// ---------------------------------------------------------------------------
// Kernel 4: final output. (pipelined global loads)
// ---------------------------------------------------------------------------
__global__ void __launch_bounds__(256)
k_final(const float* __restrict__ ws, const float* __restrict__ wm,
        float* __restrict__ out)
{
    __shared__ float4 wa4[16][4];

    const int b  = blockIdx.y;
    const int i0 = blockIdx.x * 16;
    const int t  = threadIdx.x;

    {
        int k = t >> 6, r = (t >> 4) & 3, il = t & 15;
        reinterpret_cast<float*>(wa4)[il * 16 + k * 4 + r] =
            g_weff[r] * g_scale[b * 4 + k]
            * g_mod[(size_t)b * FFDIM + k * 2048 + r * 512 + (i0 + il)];
    }

    float sbv[4][4];
#pragma unroll
    for (int k = 0; k < 4; k++) {
        float sc = g_scale[b * 4 + k];
#pragma unroll
        for (int r = 0; r < 4; r++)
            sbv[k][r] = sc * g_mod[(size_t)b * FFDIM + k * 2048 + r * 512 + HDIM + t];
    }
    __syncthreads();

    float msum = 0.f;
#pragma unroll
    for (int q = 0; q < 16; q++) msum += g_magpart[b * 16 + q];
    const float inv = rsqrtf(msum * (1.0f / 65536.0f) + EPSC);
    const float be = g_beff;

    float wmc[4]; float2 A0c, A1c;
    {
        const int pix = (i0 << 8) + t;
#pragma unroll
        for (int k = 0; k < 4; k++) wmc[k] = wm[(k << 16) + pix];
        A0c = *reinterpret_cast<const float2*>(&ws[2 * pix]);
        A1c = *reinterpret_cast<const float2*>(&ws[131072 + 2 * pix]);
    }
#pragma unroll
    for (int il = 0; il < 16; il++) {
        float wmn[4]; float2 A0n, A1n;
        if (il < 15) {
            const int pixn = ((i0 + il + 1) << 8) + t;
#pragma unroll
            for (int k = 0; k < 4; k++) wmn[k] = wm[(k << 16) + pixn];
            A0n = *reinterpret_cast<const float2*>(&ws[2 * pixn]);
            A1n = *reinterpret_cast<const float2*>(&ws[131072 + 2 * pixn]);
        }
        const int pix = ((i0 + il) << 8) + t;
        float m[4];
#pragma unroll
        for (int k = 0; k < 4; k++) {
            float4 wk = wa4[il][k];
            float acc = be;
            acc = fmaf(wk.x, sbv[k][0], acc);
            acc = fmaf(wk.y, sbv[k][1], acc);
            acc = fmaf(wk.z, sbv[k][2], acc);
            acc = fmaf(wk.w, sbv[k][3], acc);
            m[k] = wmc[k] * acc;
        }
        float re = A1c.x * m[0] - A1c.y * m[1];
        float im = A1c.x * m[1] - A1c.y * m[0];
        float mwre = fmaf(re, inv, A0c.x);
        float mwim = fmaf(im, inv, A0c.y);
        float den = sqrtf(fmaf(m[2], m[2], fmaf(m[3], m[3], EPSC)));
        out[((size_t)b << 16) + pix] =
            __fdividef(fmaf(mwre, m[2], mwim * m[3]), den);
#pragma unroll
        for (int k = 0; k < 4; k++) wmc[k] = wmn[k];
        A0c = A0n; A1c = A1n;
    }
}

// ---------------------------------------------------------------------------
// Launch
// ---------------------------------------------------------------------------
extern "C" void kernel_launch(void* const* d_in, const int* in_sizes, int n_in,
                              void* d_out, int out_size)
{
    const float* x      = (const float*)d_in[0];
    const float* Wt     = (const float*)d_in[1];
    const float* Wg     = (const float*)d_in[2];
    const float* ws     = (const float*)d_in[3];
    const float* wm     = (const float*)d_in[4];
    const float* conv_w = (const float*)d_in[5];
    const float* conv_b = (const float*)d_in[6];
    float* out = (float*)d_out;

    cudaFuncSetAttribute(k_gemm_mma,
                         cudaFuncAttributeMaxDynamicSharedMemorySize,
                         GEMM_SMEM_BYTES);

    k_xsplit<<<64, 256>>>(x);
    k_gemm_mma<<<FFDIM / 64, 256, GEMM_SMEM_BYTES>>>(Wt, Wg);
    k_scale<<<BATCH * 4, 256>>>(conv_w, conv_b);
    k_mag<<<dim3(16, BATCH), 256>>>(ws, wm);
    k_final<<<dim3(16, BATCH), 256>>>(ws, wm, out);
}